// round 10
// baseline (speedup 1.0000x reference)
#include <cuda_runtime.h>
#include <cuda_fp16.h>
#include <cstdint>

#define B_  512
#define D_  1024
#define H1_ 512
#define H2_ 128
#define BH  (B_ / 2)                    // 256, batch half

// ---- scratch (device globals: allocation-free rule) ----
__device__ float g_c1 [B_ * H1_];
__device__ float g_s1p[B_ * H1_];
__device__ float g_s2p[B_ * H2_];
__device__ float g_c3 [B_ * H1_];
__device__ __half g_a_frag[(size_t)B_ * H2_ * H1_];
__device__ __half g_b_frag[(size_t)D_ * H1_];
__device__ float  g_w2_frag[H2_ * H1_];
__device__ __half g_c3_frag[B_ * H1_];

__device__ __forceinline__ float sigm(float v) { return 1.0f / (1.0f + expf(-v)); }

__device__ __forceinline__ uint32_t packh2(float a, float b) {
    __half2 t = __floats2half2_rn(a, b);
    return *reinterpret_cast<uint32_t*>(&t);
}
__device__ __forceinline__ void mma_f16(float* c, const uint32_t* a,
                                        uint32_t b0, uint32_t b1) {
    asm volatile("mma.sync.aligned.m16n8k16.row.col.f32.f16.f16.f32 "
                 "{%0,%1,%2,%3}, {%4,%5,%6,%7}, {%8,%9}, {%0,%1,%2,%3};"
                 : "+f"(c[0]), "+f"(c[1]), "+f"(c[2]), "+f"(c[3])
                 : "r"(a[0]), "r"(a[1]), "r"(a[2]), "r"(a[3]), "r"(b0), "r"(b1));
}

// ============================================================================
// B fragment pack: W1 [H1 (k), D (n)] f32 -> g_b_frag (tile = 512B).
// ============================================================================
__global__ __launch_bounds__(256)
void w1_frag_kernel(const float* __restrict__ W1, __half* __restrict__ gB) {
    const int t = blockIdx.x * 8 + (threadIdx.x >> 5);
    const int n16 = t >> 5, kt = t & 31;
    const int lane = threadIdx.x & 31;
    const int n0 = n16 * 16 + (lane >> 2);
    const int kb = kt * 16 + 2 * (lane & 3);

    const float* Wk0 = W1 + (size_t)kb * D_;
    uint32_t p0 = packh2(Wk0[n0],              Wk0[D_ + n0]);
    uint32_t p1 = packh2(Wk0[8 * D_ + n0],     Wk0[9 * D_ + n0]);
    uint32_t p2 = packh2(Wk0[n0 + 8],          Wk0[D_ + n0 + 8]);
    uint32_t p3 = packh2(Wk0[8 * D_ + n0 + 8], Wk0[9 * D_ + n0 + 8]);

    *(uint4*)(gB + (size_t)t * 256 + lane * 8) = make_uint4(p0, p1, p2, p3);
}

// ============================================================================
// W2 fragment pre-permute (input-only, once).
// ============================================================================
__global__ __launch_bounds__(256)
void w2_frag_kernel(const float* __restrict__ W2, float* __restrict__ w2f) {
    const int kt = blockIdx.x;
    const int mt = threadIdx.x >> 5;
    const int lane = threadIdx.x & 31;
    const int r0 = mt * 16 + (lane >> 2);
    const int kb = kt * 16 + 2 * (lane & 3);
    const float* w2a = W2 + (size_t)r0 * H1_;
    const float* w2b = w2a + 8 * H1_;
    float* dst = w2f + ((size_t)kt * 8 + mt) * 256 + lane * 8;
    *(float4*)(dst)     = make_float4(w2a[kb],     w2a[kb + 1], w2b[kb],     w2b[kb + 1]);
    *(float4*)(dst + 4) = make_float4(w2a[kb + 8], w2a[kb + 9], w2b[kb + 8], w2b[kb + 9]);
}

// ============================================================================
// A fragment pack (coalesced), per batch-half via pointer offsets.
// grid = BH * 32 blocks.
// ============================================================================
__global__ __launch_bounds__(256)
void a_frag_kernel(const float* __restrict__ w2f, const float* __restrict__ s1p,
                   __half* __restrict__ gA) {
    const int b  = blockIdx.x >> 5;
    const int kt = blockIdx.x & 31;
    const int w  = threadIdx.x >> 5;
    const int lane = threadIdx.x & 31;
    const int kb = kt * 16 + 2 * (lane & 3);

    const float* s = s1p + (size_t)b * H1_;
    const float s0 = s[kb], s1v = s[kb + 1], s8 = s[kb + 8], s9 = s[kb + 9];
    const float* src = w2f + ((size_t)kt * 8 + w) * 256 + lane * 8;
    float4 f0 = *(const float4*)(src);
    float4 f1 = *(const float4*)(src + 4);

    uint32_t p0 = packh2(f0.x * s0, f0.y * s1v);
    uint32_t p1 = packh2(f0.z * s0, f0.w * s1v);
    uint32_t p2 = packh2(f1.x * s8, f1.y * s9);
    uint32_t p3 = packh2(f1.z * s8, f1.w * s9);

    const size_t tile = ((size_t)blockIdx.x * 8 + w);
    *(uint4*)(gA + tile * 256 + lane * 8) = make_uint4(p0, p1, p2, p3);
}

// ============================================================================
// c3 fragment pack: c3 [512,512] f32 -> A-fragments [kt=32][mt=32].
// ============================================================================
__global__ __launch_bounds__(256)
void c3_frag_kernel(const float* __restrict__ c3, __half* __restrict__ gA) {
    const int t = blockIdx.x * 8 + (threadIdx.x >> 5);
    const int kt = t >> 5, mt = t & 31;
    const int lane = threadIdx.x & 31;
    const int r0 = mt * 16 + (lane >> 2);
    const int kb = kt * 16 + 2 * (lane & 3);
    const float* ca = c3 + (size_t)r0 * H1_;
    const float* cb = ca + 8 * H1_;
    uint32_t p0 = packh2(ca[kb],     ca[kb + 1]);
    uint32_t p1 = packh2(cb[kb],     cb[kb + 1]);
    uint32_t p2 = packh2(ca[kb + 8], ca[kb + 9]);
    uint32_t p3 = packh2(cb[kb + 8], cb[kb + 9]);
    *(uint4*)(gA + (size_t)t * 256 + lane * 8) = make_uint4(p0, p1, p2, p3);
}

// ============================================================================
// Jac GEMM, fragment-direct with manual register double-buffering.
// grid (4, BH); per batch-half via pointer offsets.
// ============================================================================
__global__ __launch_bounds__(256, 1)
void jac_mma_kernel(const __half* __restrict__ gA,
                    const __half* __restrict__ gB,
                    const float* __restrict__ s2p,
                    float* __restrict__ jac) {
    const int tid = threadIdx.x;
    const int wid = tid >> 5;
    const int lane = tid & 31;
    const int wm = wid >> 2;
    const int wn = wid & 3;
    const int b  = blockIdx.y;
    const int n0 = blockIdx.x * 256;

    const __half* Ab = gA + (size_t)b * (32 * 8 * 256) + lane * 8
                       + (size_t)(wm * 4) * 256;
    const __half* Bb = gB + (size_t)((n0 >> 4) + wn * 4) * (32 * 256) + lane * 8;

    float acc[4][8][4] = {};
    uint4 avA[4], bvA[4], avB[4], bvB[4];

    auto loadf = [&](uint4* av, uint4* bv, int kt) {
#pragma unroll
        for (int mt = 0; mt < 4; mt++)
            av[mt] = *(const uint4*)(Ab + ((size_t)kt * 8 + mt) * 256);
#pragma unroll
        for (int np = 0; np < 4; np++)
            bv[np] = *(const uint4*)(Bb + ((size_t)np * 32 + kt) * 256);
    };
    auto domma = [&](const uint4* av, const uint4* bv) {
#pragma unroll
        for (int mt = 0; mt < 4; mt++) {
            const uint32_t* ap = reinterpret_cast<const uint32_t*>(&av[mt]);
#pragma unroll
            for (int np = 0; np < 4; np++) {
                mma_f16(acc[mt][np * 2 + 0], ap, bv[np].x, bv[np].y);
                mma_f16(acc[mt][np * 2 + 1], ap, bv[np].z, bv[np].w);
            }
        }
    };

    loadf(avA, bvA, 0);
#pragma unroll 2
    for (int kt = 0; kt < 32; kt += 2) {
        loadf(avB, bvB, kt + 1);
        domma(avA, bvA);
        if (kt + 2 < 32) loadf(avA, bvA, kt + 2);
        domma(avB, bvB);
    }

    const int g = lane >> 2;
    const int cq = 2 * (lane & 3);
#pragma unroll
    for (int mt = 0; mt < 4; mt++) {
        const int r0 = wm * 64 + mt * 16 + g;
        const float s0 = s2p[(size_t)b * H2_ + r0];
        const float s1 = s2p[(size_t)b * H2_ + r0 + 8];
        float* row0 = jac + ((size_t)b * H2_ + r0) * D_ + n0;
        float* row1 = row0 + 8 * D_;
#pragma unroll
        for (int nt = 0; nt < 8; nt++) {
            const int col = wn * 64 + nt * 8 + cq;
            *(float2*)(row0 + col) = make_float2(acc[mt][nt][0] * s0, acc[mt][nt][1] * s0);
            *(float2*)(row1 + col) = make_float2(acc[mt][nt][2] * s1, acc[mt][nt][3] * s1);
        }
    }
}

// ============================================================================
// recover = c3 @ W1 + b_r via fragment-direct mma; reuses g_b_frag.
// ============================================================================
__global__ __launch_bounds__(256, 1)
void recover_mma_kernel(const __half* __restrict__ gA,
                        const __half* __restrict__ gB,
                        const float* __restrict__ b_r,
                        float* __restrict__ out) {
    const int tid = threadIdx.x;
    const int wid = tid >> 5;
    const int lane = tid & 31;
    const int wm = wid >> 2;
    const int wn = wid & 3;
    const int m0 = blockIdx.y * 128;
    const int n0 = blockIdx.x * 256;

    const int mtb = (m0 >> 4) + wm * 4;
    const int n16base = (n0 >> 4) + wn * 4;

    float acc[4][8][4] = {};

    #pragma unroll 2
    for (int kt = 0; kt < 32; kt++) {
        uint4 av[4], bv[4];
#pragma unroll
        for (int mt = 0; mt < 4; mt++)
            av[mt] = *(const uint4*)(gA + ((size_t)kt * 32 + mtb + mt) * 256
                                     + lane * 8);
#pragma unroll
        for (int np = 0; np < 4; np++)
            bv[np] = *(const uint4*)(gB + ((size_t)(n16base + np) * 32 + kt) * 256
                                     + lane * 8);
#pragma unroll
        for (int mt = 0; mt < 4; mt++) {
            const uint32_t* ap = reinterpret_cast<const uint32_t*>(&av[mt]);
#pragma unroll
            for (int np = 0; np < 4; np++) {
                mma_f16(acc[mt][np * 2 + 0], ap, bv[np].x, bv[np].y);
                mma_f16(acc[mt][np * 2 + 1], ap, bv[np].z, bv[np].w);
            }
        }
    }

    const int g = lane >> 2;
    const int cq = 2 * (lane & 3);
#pragma unroll
    for (int mt = 0; mt < 4; mt++) {
        const int r0 = m0 + wm * 64 + mt * 16 + g;
        float* row0 = out + (size_t)r0 * D_ + n0;
        float* row1 = row0 + 8 * D_;
#pragma unroll
        for (int nt = 0; nt < 8; nt++) {
            const int col = wn * 64 + nt * 8 + cq;
            const float bc0 = b_r[n0 + col], bc1 = b_r[n0 + col + 1];
            *(float2*)(row0 + col) = make_float2(acc[mt][nt][0] + bc0, acc[mt][nt][1] + bc1);
            *(float2*)(row1 + col) = make_float2(acc[mt][nt][2] + bc0, acc[mt][nt][3] + bc1);
        }
    }
}

// ============================================================================
// Small generic SGEMM (scalar), unchanged.
// ============================================================================
template <int ACT, bool TB>
__global__ __launch_bounds__(256)
void sgemm64(const float* __restrict__ A, const float* __restrict__ Bm,
             const float* __restrict__ bias, float* __restrict__ C,
             float* __restrict__ S, int M, int N, int K) {
    constexpr int BM = 64, BN = 64, BK = 16;
    __shared__ __align__(16) float As[BK][BM + 4];
    __shared__ __align__(16) float Bs[BK][BN + 4];

    const int tid = threadIdx.x;
    const int m0 = blockIdx.y * BM;
    const int n0 = blockIdx.x * BN;

    const int ak = tid & 15;
    const int am = tid >> 4;
    const int rowBase = (tid >> 4) * 4;
    const int colBase = (tid & 15) * 4;

    float acc[4][4] = {};
    float ra[4], rb[4];
    const int NT = K / BK;

    auto loadA = [&](int t) {
        const int kt = t * BK;
#pragma unroll
        for (int j = 0; j < 4; j++)
            ra[j] = A[(size_t)(m0 + am + 16 * j) * K + kt + ak];
    };
    auto loadB = [&](int t) {
        const int kt = t * BK;
        if (TB) {
#pragma unroll
            for (int j = 0; j < 4; j++)
                rb[j] = Bm[(size_t)(n0 + am + 16 * j) * K + kt + ak];
        } else {
#pragma unroll
            for (int j = 0; j < 4; j++)
                rb[j] = Bm[(size_t)(kt + (tid >> 6) + 4 * j) * N + n0 + (tid & 63)];
        }
    };
    auto storeA = [&]() {
#pragma unroll
        for (int j = 0; j < 4; j++) As[ak][am + 16 * j] = ra[j];
    };
    auto storeB = [&]() {
        if (TB) {
#pragma unroll
            for (int j = 0; j < 4; j++) Bs[ak][am + 16 * j] = rb[j];
        } else {
#pragma unroll
            for (int j = 0; j < 4; j++) Bs[(tid >> 6) + 4 * j][tid & 63] = rb[j];
        }
    };

    loadA(0); loadB(0);
    storeA(); storeB();
    __syncthreads();

    for (int t = 0; t < NT; t++) {
        if (t + 1 < NT) { loadA(t + 1); loadB(t + 1); }
#pragma unroll
        for (int kk = 0; kk < BK; kk++) {
            float a[4], bq[4];
            *(float4*)a  = *(const float4*)&As[kk][rowBase];
            *(float4*)bq = *(const float4*)&Bs[kk][colBase];
#pragma unroll
            for (int i = 0; i < 4; i++)
#pragma unroll
                for (int j = 0; j < 4; j++)
                    acc[i][j] += a[i] * bq[j];
        }
        __syncthreads();
        if (t + 1 < NT) { storeA(); storeB(); __syncthreads(); }
    }

#pragma unroll
    for (int i = 0; i < 4; i++) {
        const int row = m0 + rowBase + i;
#pragma unroll
        for (int j = 0; j < 4; j++) {
            const int col = n0 + colBase + j;
            float v = acc[i][j] + bias[col];
            if (ACT == 0) {
                C[(size_t)row * N + col] = v;
            } else if (ACT == 1) {
                C[(size_t)row * N + col] = sigm(v);
            } else {
                float c = sigm(v);
                C[(size_t)row * N + col] = c;
                S[(size_t)row * N + col] = c * (1.0f - c);
            }
        }
    }
}

// ============================================================================
// Streams/events (created once, on the first — non-captured — call).
// ============================================================================
struct Aux {
    cudaStream_t s1;
    cudaEvent_t e0, e1h0, e2h0, e1h1, e2h1, etail;
    Aux() {
        cudaStreamCreateWithFlags(&s1, cudaStreamNonBlocking);
        cudaEventCreateWithFlags(&e0,   cudaEventDisableTiming);
        cudaEventCreateWithFlags(&e1h0, cudaEventDisableTiming);
        cudaEventCreateWithFlags(&e2h0, cudaEventDisableTiming);
        cudaEventCreateWithFlags(&e1h1, cudaEventDisableTiming);
        cudaEventCreateWithFlags(&e2h1, cudaEventDisableTiming);
        cudaEventCreateWithFlags(&etail, cudaEventDisableTiming);
    }
};

extern "C" void kernel_launch(void* const* d_in, const int* in_sizes, int n_in,
                              void* d_out, int out_size) {
    const float* x   = (const float*)d_in[0];
    const float* W1  = (const float*)d_in[1];
    const float* b1  = (const float*)d_in[2];
    const float* W2  = (const float*)d_in[3];
    const float* b2  = (const float*)d_in[4];
    const float* b3  = (const float*)d_in[5];
    const float* b_r = (const float*)d_in[6];

    float* out     = (float*)d_out;
    float* recover = out;
    float* c2      = out + (size_t)B_ * D_;
    float* jac     = c2 + (size_t)B_ * H2_;

    float *c1, *s1p, *s2p, *c3, *w2f;
    __half *a_frag, *b_frag, *c3_frag;
    cudaGetSymbolAddress((void**)&c1,  g_c1);
    cudaGetSymbolAddress((void**)&s1p, g_s1p);
    cudaGetSymbolAddress((void**)&s2p, g_s2p);
    cudaGetSymbolAddress((void**)&c3,  g_c3);
    cudaGetSymbolAddress((void**)&w2f, g_w2_frag);
    cudaGetSymbolAddress((void**)&a_frag, g_a_frag);
    cudaGetSymbolAddress((void**)&b_frag, g_b_frag);
    cudaGetSymbolAddress((void**)&c3_frag, g_c3_frag);

    static Aux aux;
    cudaStream_t s0 = 0, s1 = aux.s1;
    dim3 blk(256);

    const size_t aHalf = (size_t)BH * (32 * 8 * 256);   // a_frag elems per half

    // fork
    cudaEventRecord(aux.e0, s0);
    cudaStreamWaitEvent(s1, aux.e0, 0);

    // s1: input-only preps, then the gemm chain, half by half
    w1_frag_kernel<<<(64 * 32) / 8, blk, 0, s1>>>(W1, b_frag);
    w2_frag_kernel<<<32, blk, 0, s1>>>(W2, w2f);

    // half 0
    sgemm64<2, true><<<dim3(H1_ / 64, BH / 64), blk, 0, s1>>>(
        x, W1, b1, c1, s1p, BH, H1_, D_);
    cudaEventRecord(aux.e1h0, s1);
    sgemm64<2, true><<<dim3(H2_ / 64, BH / 64), blk, 0, s1>>>(
        c1, W2, b2, c2, s2p, BH, H2_, H1_);
    cudaEventRecord(aux.e2h0, s1);
    // half 1
    sgemm64<2, true><<<dim3(H1_ / 64, BH / 64), blk, 0, s1>>>(
        x + (size_t)BH * D_, W1, b1, c1 + (size_t)BH * H1_,
        s1p + (size_t)BH * H1_, BH, H1_, D_);
    cudaEventRecord(aux.e1h1, s1);
    sgemm64<2, true><<<dim3(H2_ / 64, BH / 64), blk, 0, s1>>>(
        c1 + (size_t)BH * H1_, W2, b2, c2 + (size_t)BH * H2_,
        s2p + (size_t)BH * H2_, BH, H2_, H1_);
    cudaEventRecord(aux.e2h1, s1);

    // s1 tail: c3 chain + recover (overlaps jac on s0)
    sgemm64<1, false><<<dim3(H1_ / 64, B_ / 64), blk, 0, s1>>>(
        c2, W2, b3, c3, nullptr, B_, H1_, H2_);
    c3_frag_kernel<<<(32 * 32) / 8, blk, 0, s1>>>(c3, c3_frag);
    recover_mma_kernel<<<dim3(D_ / 256, B_ / 128), blk, 0, s1>>>(
        c3_frag, b_frag, b_r, recover);
    cudaEventRecord(aux.etail, s1);

    // s0: a_frag + jac per half
    cudaStreamWaitEvent(s0, aux.e1h0, 0);
    a_frag_kernel<<<BH * 32, blk, 0, s0>>>(w2f, s1p, a_frag);
    cudaStreamWaitEvent(s0, aux.e2h0, 0);
    jac_mma_kernel<<<dim3(D_ / 256, BH), blk, 0, s0>>>(a_frag, b_frag, s2p, jac);

    cudaStreamWaitEvent(s0, aux.e1h1, 0);
    a_frag_kernel<<<BH * 32, blk, 0, s0>>>(w2f, s1p + (size_t)BH * H1_,
                                           a_frag + aHalf);
    cudaStreamWaitEvent(s0, aux.e2h1, 0);
    jac_mma_kernel<<<dim3(D_ / 256, BH), blk, 0, s0>>>(
        a_frag + aHalf, b_frag, s2p + (size_t)BH * H2_,
        jac + (size_t)BH * H2_ * D_);

    // join
    cudaStreamWaitEvent(s0, aux.etail, 0);
}

// round 11
// speedup vs baseline: 1.2570x; 1.2570x over previous
#include <cuda_runtime.h>
#include <cuda_fp16.h>
#include <cstdint>

#define B_  512
#define D_  1024
#define H1_ 512
#define H2_ 128

// ---- scratch (device globals: allocation-free rule) ----
__device__ float g_c1 [B_ * H1_];
__device__ float g_s1p[B_ * H1_];
__device__ float g_s2p[B_ * H2_];
__device__ float g_c3 [B_ * H1_];
__device__ float g_part1[4 * B_ * H1_];                // split-K partials gemm1
__device__ float g_part2[4 * B_ * H2_];                // split-K partials gemm2
__device__ __half g_b_frag[(size_t)D_ * H1_];
__device__ float  g_w2_frag[H2_ * H1_];
__device__ __half g_c3_frag[B_ * H1_];

__device__ __forceinline__ float sigm(float v) { return 1.0f / (1.0f + expf(-v)); }

__device__ __forceinline__ uint32_t packh2(float a, float b) {
    __half2 t = __floats2half2_rn(a, b);
    return *reinterpret_cast<uint32_t*>(&t);
}
__device__ __forceinline__ void mma_f16(float* c, const uint32_t* a,
                                        uint32_t b0, uint32_t b1) {
    asm volatile("mma.sync.aligned.m16n8k16.row.col.f32.f16.f16.f32 "
                 "{%0,%1,%2,%3}, {%4,%5,%6,%7}, {%8,%9}, {%0,%1,%2,%3};"
                 : "+f"(c[0]), "+f"(c[1]), "+f"(c[2]), "+f"(c[3])
                 : "r"(a[0]), "r"(a[1]), "r"(a[2]), "r"(a[3]), "r"(b0), "r"(b1));
}

// ============================================================================
// B fragment pack: W1 [H1 (k), D (n)] f32 -> g_b_frag (tile = 512B).
// ============================================================================
__global__ __launch_bounds__(256)
void w1_frag_kernel(const float* __restrict__ W1, __half* __restrict__ gB) {
    const int t = blockIdx.x * 8 + (threadIdx.x >> 5);
    const int n16 = t >> 5, kt = t & 31;
    const int lane = threadIdx.x & 31;
    const int n0 = n16 * 16 + (lane >> 2);
    const int kb = kt * 16 + 2 * (lane & 3);

    const float* Wk0 = W1 + (size_t)kb * D_;
    uint32_t p0 = packh2(Wk0[n0],              Wk0[D_ + n0]);
    uint32_t p1 = packh2(Wk0[8 * D_ + n0],     Wk0[9 * D_ + n0]);
    uint32_t p2 = packh2(Wk0[n0 + 8],          Wk0[D_ + n0 + 8]);
    uint32_t p3 = packh2(Wk0[8 * D_ + n0 + 8], Wk0[9 * D_ + n0 + 8]);

    *(uint4*)(gB + (size_t)t * 256 + lane * 8) = make_uint4(p0, p1, p2, p3);
}

// ============================================================================
// W2 fragment pre-permute (input-only, once). Layout [kt=32][mt=8], 1KB/tile.
// ============================================================================
__global__ __launch_bounds__(256)
void w2_frag_kernel(const float* __restrict__ W2, float* __restrict__ w2f) {
    const int kt = blockIdx.x;
    const int mt = threadIdx.x >> 5;
    const int lane = threadIdx.x & 31;
    const int r0 = mt * 16 + (lane >> 2);
    const int kb = kt * 16 + 2 * (lane & 3);
    const float* w2a = W2 + (size_t)r0 * H1_;
    const float* w2b = w2a + 8 * H1_;
    float* dst = w2f + ((size_t)kt * 8 + mt) * 256 + lane * 8;
    *(float4*)(dst)     = make_float4(w2a[kb],     w2a[kb + 1], w2b[kb],     w2b[kb + 1]);
    *(float4*)(dst + 4) = make_float4(w2a[kb + 8], w2a[kb + 9], w2b[kb + 8], w2b[kb + 9]);
}

// ============================================================================
// c3 fragment pack: c3 [512,512] f32 -> A-fragments [kt=32][mt=32].
// ============================================================================
__global__ __launch_bounds__(256)
void c3_frag_kernel(const float* __restrict__ c3, __half* __restrict__ gA) {
    const int t = blockIdx.x * 8 + (threadIdx.x >> 5);
    const int kt = t >> 5, mt = t & 31;
    const int lane = threadIdx.x & 31;
    const int r0 = mt * 16 + (lane >> 2);
    const int kb = kt * 16 + 2 * (lane & 3);
    const float* ca = c3 + (size_t)r0 * H1_;
    const float* cb = ca + 8 * H1_;
    uint32_t p0 = packh2(ca[kb],     ca[kb + 1]);
    uint32_t p1 = packh2(cb[kb],     cb[kb + 1]);
    uint32_t p2 = packh2(ca[kb + 8], ca[kb + 9]);
    uint32_t p3 = packh2(cb[kb + 8], cb[kb + 9]);
    *(uint4*)(gA + (size_t)t * 256 + lane * 8) = make_uint4(p0, p1, p2, p3);
}

// ============================================================================
// Split-K partial SGEMM (TB): P[z][m][n] = sum_{k in chunk z} A[m,k]*B[n,k].
// grid (N/64, M/64, 4); raw partials, no bias/activation.
// ============================================================================
__global__ __launch_bounds__(256)
void sgemm_part_kernel(const float* __restrict__ A, const float* __restrict__ Bm,
                       float* __restrict__ P, int M, int N, int K) {
    constexpr int BM = 64, BN = 64, BK = 16;
    __shared__ __align__(16) float As[BK][BM + 4];
    __shared__ __align__(16) float Bs[BK][BN + 4];

    const int tid = threadIdx.x;
    const int m0 = blockIdx.y * BM;
    const int n0 = blockIdx.x * BN;
    const int kbase = blockIdx.z * (K / 4);

    const int ak = tid & 15;
    const int am = tid >> 4;
    const int rowBase = (tid >> 4) * 4;
    const int colBase = (tid & 15) * 4;

    float acc[4][4] = {};
    float ra[4], rb[4];
    const int NT = (K / 4) / BK;

    auto loadA = [&](int t) {
        const int kt = kbase + t * BK;
#pragma unroll
        for (int j = 0; j < 4; j++)
            ra[j] = A[(size_t)(m0 + am + 16 * j) * K + kt + ak];
    };
    auto loadB = [&](int t) {
        const int kt = kbase + t * BK;
#pragma unroll
        for (int j = 0; j < 4; j++)
            rb[j] = Bm[(size_t)(n0 + am + 16 * j) * K + kt + ak];
    };
    auto storeAB = [&]() {
#pragma unroll
        for (int j = 0; j < 4; j++) As[ak][am + 16 * j] = ra[j];
#pragma unroll
        for (int j = 0; j < 4; j++) Bs[ak][am + 16 * j] = rb[j];
    };

    loadA(0); loadB(0);
    storeAB();
    __syncthreads();

    for (int t = 0; t < NT; t++) {
        if (t + 1 < NT) { loadA(t + 1); loadB(t + 1); }
#pragma unroll
        for (int kk = 0; kk < BK; kk++) {
            float a[4], bq[4];
            *(float4*)a  = *(const float4*)&As[kk][rowBase];
            *(float4*)bq = *(const float4*)&Bs[kk][colBase];
#pragma unroll
            for (int i = 0; i < 4; i++)
#pragma unroll
                for (int j = 0; j < 4; j++)
                    acc[i][j] += a[i] * bq[j];
        }
        __syncthreads();
        if (t + 1 < NT) { storeAB(); __syncthreads(); }
    }

    float* Pz = P + (size_t)blockIdx.z * M * N;
#pragma unroll
    for (int i = 0; i < 4; i++) {
        const int row = m0 + rowBase + i;
#pragma unroll
        for (int j = 0; j < 4; j++)
            Pz[(size_t)row * N + n0 + colBase + j] = acc[i][j];
    }
}

// ============================================================================
// Reduce 4 partials + bias -> sigmoid (+ derivative). N power of two.
// grid: MN/1024 blocks, 4 elems/thread (float4).
// ============================================================================
__global__ __launch_bounds__(256)
void reduce_act_kernel(const float* __restrict__ P, const float* __restrict__ bias,
                       float* __restrict__ C, float* __restrict__ S,
                       int MN, int Nmask) {
    const int idx = (blockIdx.x * 256 + threadIdx.x) * 4;
    float4 v0 = *(const float4*)(P + idx);
    float4 v1 = *(const float4*)(P + MN + idx);
    float4 v2 = *(const float4*)(P + 2 * MN + idx);
    float4 v3 = *(const float4*)(P + 3 * MN + idx);
    float4 bb = *(const float4*)(bias + (idx & Nmask));
    float4 c;
    c.x = sigm(v0.x + v1.x + v2.x + v3.x + bb.x);
    c.y = sigm(v0.y + v1.y + v2.y + v3.y + bb.y);
    c.z = sigm(v0.z + v1.z + v2.z + v3.z + bb.z);
    c.w = sigm(v0.w + v1.w + v2.w + v3.w + bb.w);
    *(float4*)(C + idx) = c;
    if (S) {
        float4 s;
        s.x = c.x * (1.0f - c.x);
        s.y = c.y * (1.0f - c.y);
        s.z = c.z * (1.0f - c.z);
        s.w = c.w * (1.0f - c.w);
        *(float4*)(S + idx) = s;
    }
}

// ============================================================================
// Jac GEMM, fragment-direct, A built on the fly from w2f (f32, L2-resident)
// and s1p (smem). grid (4, 512); 8 warps, warp tile 64x64.
// ============================================================================
__global__ __launch_bounds__(256, 1)
void jac_mma_kernel(const float* __restrict__ w2f,
                    const float* __restrict__ s1p,
                    const __half* __restrict__ gB,
                    const float* __restrict__ s2p,
                    float* __restrict__ jac) {
    __shared__ float ss[H1_];
    const int tid = threadIdx.x;
    const int wid = tid >> 5;
    const int lane = tid & 31;
    const int wm = wid >> 2;
    const int wn = wid & 3;
    const int b  = blockIdx.y;
    const int n0 = blockIdx.x * 256;

    for (int i = tid; i < H1_; i += 256) ss[i] = s1p[(size_t)b * H1_ + i];
    __syncthreads();

    const float* Aw = w2f + (size_t)(wm * 4) * 256 + lane * 8;
    const __half* Bb = gB + (size_t)((n0 >> 4) + wn * 4) * (32 * 256) + lane * 8;
    const int klo = 2 * (lane & 3);

    float acc[4][8][4] = {};

    #pragma unroll 2
    for (int kt = 0; kt < 32; kt++) {
        const int kb = kt * 16 + klo;
        const float s0 = ss[kb], s1v = ss[kb + 1];
        const float s8 = ss[kb + 8], s9 = ss[kb + 9];

        uint32_t a[4][4];
        uint4 bv[4];
#pragma unroll
        for (int mt = 0; mt < 4; mt++) {
            const float* src = Aw + ((size_t)kt * 8 + mt) * 256;
            float4 f0 = *(const float4*)(src);
            float4 f1 = *(const float4*)(src + 4);
            a[mt][0] = packh2(f0.x * s0, f0.y * s1v);
            a[mt][1] = packh2(f0.z * s0, f0.w * s1v);
            a[mt][2] = packh2(f1.x * s8, f1.y * s9);
            a[mt][3] = packh2(f1.z * s8, f1.w * s9);
        }
#pragma unroll
        for (int np = 0; np < 4; np++)
            bv[np] = *(const uint4*)(Bb + ((size_t)np * 32 + kt) * 256);
#pragma unroll
        for (int mt = 0; mt < 4; mt++) {
#pragma unroll
            for (int np = 0; np < 4; np++) {
                mma_f16(acc[mt][np * 2 + 0], a[mt], bv[np].x, bv[np].y);
                mma_f16(acc[mt][np * 2 + 1], a[mt], bv[np].z, bv[np].w);
            }
        }
    }

    const int g = lane >> 2;
    const int cq = 2 * (lane & 3);
#pragma unroll
    for (int mt = 0; mt < 4; mt++) {
        const int r0 = wm * 64 + mt * 16 + g;
        const float s0 = s2p[(size_t)b * H2_ + r0];
        const float s1 = s2p[(size_t)b * H2_ + r0 + 8];
        float* row0 = jac + ((size_t)b * H2_ + r0) * D_ + n0;
        float* row1 = row0 + 8 * D_;
#pragma unroll
        for (int nt = 0; nt < 8; nt++) {
            const int col = wn * 64 + nt * 8 + cq;
            *(float2*)(row0 + col) = make_float2(acc[mt][nt][0] * s0, acc[mt][nt][1] * s0);
            *(float2*)(row1 + col) = make_float2(acc[mt][nt][2] * s1, acc[mt][nt][3] * s1);
        }
    }
}

// ============================================================================
// recover = c3 @ W1 + b_r via fragment-direct mma; reuses g_b_frag.
// ============================================================================
__global__ __launch_bounds__(256, 1)
void recover_mma_kernel(const __half* __restrict__ gA,
                        const __half* __restrict__ gB,
                        const float* __restrict__ b_r,
                        float* __restrict__ out) {
    const int tid = threadIdx.x;
    const int wid = tid >> 5;
    const int lane = tid & 31;
    const int wm = wid >> 2;
    const int wn = wid & 3;
    const int m0 = blockIdx.y * 128;
    const int n0 = blockIdx.x * 256;

    const int mtb = (m0 >> 4) + wm * 4;
    const int n16base = (n0 >> 4) + wn * 4;

    float acc[4][8][4] = {};

    #pragma unroll 2
    for (int kt = 0; kt < 32; kt++) {
        uint4 av[4], bv[4];
#pragma unroll
        for (int mt = 0; mt < 4; mt++)
            av[mt] = *(const uint4*)(gA + ((size_t)kt * 32 + mtb + mt) * 256
                                     + lane * 8);
#pragma unroll
        for (int np = 0; np < 4; np++)
            bv[np] = *(const uint4*)(gB + ((size_t)(n16base + np) * 32 + kt) * 256
                                     + lane * 8);
#pragma unroll
        for (int mt = 0; mt < 4; mt++) {
            const uint32_t* ap = reinterpret_cast<const uint32_t*>(&av[mt]);
#pragma unroll
            for (int np = 0; np < 4; np++) {
                mma_f16(acc[mt][np * 2 + 0], ap, bv[np].x, bv[np].y);
                mma_f16(acc[mt][np * 2 + 1], ap, bv[np].z, bv[np].w);
            }
        }
    }

    const int g = lane >> 2;
    const int cq = 2 * (lane & 3);
#pragma unroll
    for (int mt = 0; mt < 4; mt++) {
        const int r0 = m0 + wm * 64 + mt * 16 + g;
        float* row0 = out + (size_t)r0 * D_ + n0;
        float* row1 = row0 + 8 * D_;
#pragma unroll
        for (int nt = 0; nt < 8; nt++) {
            const int col = wn * 64 + nt * 8 + cq;
            const float bc0 = b_r[n0 + col], bc1 = b_r[n0 + col + 1];
            *(float2*)(row0 + col) = make_float2(acc[mt][nt][0] + bc0, acc[mt][nt][1] + bc1);
            *(float2*)(row1 + col) = make_float2(acc[mt][nt][2] + bc0, acc[mt][nt][3] + bc1);
        }
    }
}

// ============================================================================
// Plain scalar SGEMM (gemm3 only: c3 = sigmoid(c2 @ W2 + b3), K=128).
// ============================================================================
__global__ __launch_bounds__(256)
void sgemm_nn_kernel(const float* __restrict__ A, const float* __restrict__ Bm,
                     const float* __restrict__ bias, float* __restrict__ C,
                     int M, int N, int K) {
    constexpr int BM = 64, BN = 64, BK = 16;
    __shared__ __align__(16) float As[BK][BM + 4];
    __shared__ __align__(16) float Bs[BK][BN + 4];

    const int tid = threadIdx.x;
    const int m0 = blockIdx.y * BM;
    const int n0 = blockIdx.x * BN;

    const int ak = tid & 15;
    const int am = tid >> 4;
    const int rowBase = (tid >> 4) * 4;
    const int colBase = (tid & 15) * 4;

    float acc[4][4] = {};
    float ra[4], rb[4];
    const int NT = K / BK;

    auto loadA = [&](int t) {
        const int kt = t * BK;
#pragma unroll
        for (int j = 0; j < 4; j++)
            ra[j] = A[(size_t)(m0 + am + 16 * j) * K + kt + ak];
    };
    auto loadB = [&](int t) {
        const int kt = t * BK;
#pragma unroll
        for (int j = 0; j < 4; j++)
            rb[j] = Bm[(size_t)(kt + (tid >> 6) + 4 * j) * N + n0 + (tid & 63)];
    };
    auto storeAB = [&]() {
#pragma unroll
        for (int j = 0; j < 4; j++) As[ak][am + 16 * j] = ra[j];
#pragma unroll
        for (int j = 0; j < 4; j++) Bs[(tid >> 6) + 4 * j][tid & 63] = rb[j];
    };

    loadA(0); loadB(0);
    storeAB();
    __syncthreads();

    for (int t = 0; t < NT; t++) {
        if (t + 1 < NT) { loadA(t + 1); loadB(t + 1); }
#pragma unroll
        for (int kk = 0; kk < BK; kk++) {
            float a[4], bq[4];
            *(float4*)a  = *(const float4*)&As[kk][rowBase];
            *(float4*)bq = *(const float4*)&Bs[kk][colBase];
#pragma unroll
            for (int i = 0; i < 4; i++)
#pragma unroll
                for (int j = 0; j < 4; j++)
                    acc[i][j] += a[i] * bq[j];
        }
        __syncthreads();
        if (t + 1 < NT) { storeAB(); __syncthreads(); }
    }

#pragma unroll
    for (int i = 0; i < 4; i++) {
        const int row = m0 + rowBase + i;
#pragma unroll
        for (int j = 0; j < 4; j++) {
            const int col = n0 + colBase + j;
            C[(size_t)row * N + col] = sigm(acc[i][j] + bias[col]);
        }
    }
}

// ============================================================================
// Streams/events (created once, on the first — non-captured — call).
// ============================================================================
struct Aux {
    cudaStream_t s1;
    cudaEvent_t e0, ew, e2, etail;
    Aux() {
        cudaStreamCreateWithFlags(&s1, cudaStreamNonBlocking);
        cudaEventCreateWithFlags(&e0,   cudaEventDisableTiming);
        cudaEventCreateWithFlags(&ew,   cudaEventDisableTiming);
        cudaEventCreateWithFlags(&e2,   cudaEventDisableTiming);
        cudaEventCreateWithFlags(&etail, cudaEventDisableTiming);
    }
};

extern "C" void kernel_launch(void* const* d_in, const int* in_sizes, int n_in,
                              void* d_out, int out_size) {
    const float* x   = (const float*)d_in[0];
    const float* W1  = (const float*)d_in[1];
    const float* b1  = (const float*)d_in[2];
    const float* W2  = (const float*)d_in[3];
    const float* b2  = (const float*)d_in[4];
    const float* b3  = (const float*)d_in[5];
    const float* b_r = (const float*)d_in[6];

    float* out     = (float*)d_out;
    float* recover = out;
    float* c2      = out + (size_t)B_ * D_;
    float* jac     = c2 + (size_t)B_ * H2_;

    float *c1, *s1p, *s2p, *c3, *w2f, *p1, *p2;
    __half *b_frag, *c3_frag;
    cudaGetSymbolAddress((void**)&c1,  g_c1);
    cudaGetSymbolAddress((void**)&s1p, g_s1p);
    cudaGetSymbolAddress((void**)&s2p, g_s2p);
    cudaGetSymbolAddress((void**)&c3,  g_c3);
    cudaGetSymbolAddress((void**)&w2f, g_w2_frag);
    cudaGetSymbolAddress((void**)&p1,  g_part1);
    cudaGetSymbolAddress((void**)&p2,  g_part2);
    cudaGetSymbolAddress((void**)&b_frag, g_b_frag);
    cudaGetSymbolAddress((void**)&c3_frag, g_c3_frag);

    static Aux aux;
    cudaStream_t s0 = 0, s1 = aux.s1;
    dim3 blk(256);

    // fork
    cudaEventRecord(aux.e0, s0);
    cudaStreamWaitEvent(s1, aux.e0, 0);

    // s1: input-only fragment preps
    w1_frag_kernel<<<(64 * 32) / 8, blk, 0, s1>>>(W1, b_frag);
    w2_frag_kernel<<<32, blk, 0, s1>>>(W2, w2f);
    cudaEventRecord(aux.ew, s1);

    // s0: gemm1 split-K (grid 256) -> reduce -> c1, s1p
    sgemm_part_kernel<<<dim3(H1_ / 64, B_ / 64, 4), blk, 0, s0>>>(
        x, W1, p1, B_, H1_, D_);
    reduce_act_kernel<<<(B_ * H1_) / 1024, blk, 0, s0>>>(
        p1, b1, c1, s1p, B_ * H1_, H1_ - 1);

    // s0: gemm2 split-K (grid 64) -> reduce -> c2, s2p
    sgemm_part_kernel<<<dim3(H2_ / 64, B_ / 64, 4), blk, 0, s0>>>(
        c1, W2, p2, B_, H2_, H1_);
    reduce_act_kernel<<<(B_ * H2_) / 1024, blk, 0, s0>>>(
        p2, b2, c2, s2p, B_ * H2_, H2_ - 1);
    cudaEventRecord(aux.e2, s0);

    // s1 tail: c3 chain + recover (hidden under jac)
    cudaStreamWaitEvent(s1, aux.e2, 0);
    sgemm_nn_kernel<<<dim3(H1_ / 64, B_ / 64), blk, 0, s1>>>(
        c2, W2, b3, c3, B_, H1_, H2_);
    c3_frag_kernel<<<(32 * 32) / 8, blk, 0, s1>>>(c3, c3_frag);
    recover_mma_kernel<<<dim3(D_ / 256, B_ / 128), blk, 0, s1>>>(
        c3_frag, b_frag, b_r, recover);
    cudaEventRecord(aux.etail, s1);

    // s0: jac (needs s1p/s2p in-order; w2f/b_frag via ew)
    cudaStreamWaitEvent(s0, aux.ew, 0);
    jac_mma_kernel<<<dim3(D_ / 256, B_), blk, 0, s0>>>(w2f, s1p, b_frag, s2p, jac);

    // join
    cudaStreamWaitEvent(s0, aux.etail, 0);
}